// round 10
// baseline (speedup 1.0000x reference)
#include <cuda_runtime.h>
#include <math.h>

// ---------------------------------------------------------------------------
// MRIEncoder fused pipeline, fp32 (rev C8: C7 + K1 x*roi staged in shared)
//   K1: per-node  x*roi -> Linear(3,128) -> GroupNorm(8) -> LeakyReLU(0.2)
//       -> Linear(128,128) -> segment max per graph        => g_z [4096,128]
//   K2: p = z @ W3 + b3  (+ per-block column sum/sumsq)    => g_p, g_part
//   K3: batch-norm stat finalize (4 blocks, fixed order)   => g_stats
//   K4: normalize+ReLU -> @W4 + b4 -> row L2 normalize     => out [4096,1024]
// All math is exact fp32 (f32x2 FMA == 2x scalar FFMA bitwise).
// ---------------------------------------------------------------------------

#define G    4096
#define NN   113
#define HID  128
#define P3   512
#define EMB  1024
#define K2R  32                 // rows per k2 block
#define K2B  (G / K2R)          // 128 k2 blocks

typedef unsigned long long ull;

__device__ float g_z[G * HID];            // 2 MB
__device__ float g_p[G * P3];             // 8 MB
__device__ float g_part[2 * K2B * P3];    // per-k2-block column sum / sumsq
__device__ float g_stats[2 * P3];         // fused scale / shift

// ---- packed fp32x2 helpers -------------------------------------------------

__device__ __forceinline__ ull pk2(float lo, float hi) {
    ull r;
    asm("mov.b64 %0, {%1, %2};" : "=l"(r) : "f"(lo), "f"(hi));
    return r;
}
__device__ __forceinline__ void upk2(ull v, float& lo, float& hi) {
    asm("mov.b64 {%0, %1}, %2;" : "=f"(lo), "=f"(hi) : "l"(v));
}
// d = a*b + d  (elementwise on two packed fp32 lanes, exact fp32 FMA)
__device__ __forceinline__ void fma2(ull& d, ull a, ull b) {
    asm("fma.rn.f32x2 %0, %1, %2, %0;" : "+l"(d) : "l"(a), "l"(b));
}

// ------------------------------- K1 ----------------------------------------
// Block = one graph, 256 threads (8 warps). Two passes of 64 node slots.
// Warp w owns node slots w*8..w*8+7 of each pass; lane owns output channels
// c0 = lane*4 .. +3.  113 nodes / 8-node granularity = 15 warp-units, which
// this schedule issues exactly (pass-2 warp 7 is skipped).
//
// Prologue stages xs[i] = x[g*339+i] * rs[i] into shared (computed once per
// element instead of redundantly in all 32 lanes; bitwise-identical product).
// Phase A reads xs via broadcast LDS -> no per-node LDGs in the hot loop.
//
// h-tile layout (shared): element (row=channel, col=node slot 0..63) lives at
//   HT2[row*64 + gp*4 + (col&3)],  gp = ((col>>2) + (row>>2)) & 15
// Phase-A stores: swizzle keeps store conflicts bounded; phase-B reads are
// warp-uniform (broadcast, conflict-free), 16B aligned -> ulonglong2 loads.
//
// Pass 0 handles slots 0..63 (< NN always) with ALL_VALID=true: all bounds
// guards and masked-max predicates compile out. Pass 1 keeps the checks.

struct SmemK1 {
    float W2[HID * HID];     // 64 KB
    float HT2[HID * 64];     // 32 KB
    float W1[3 * HID];
    float b1[HID];
    float gg[HID];
    float gb[HID];
    float b2[HID];
    float xs[NN * 3 + 1];    // x * roi_scaler for this graph
    float wmax[8][HID];
};

template <bool ALL_VALID>
__device__ __forceinline__ void k1_pass(
    SmemK1& s, int w, int lane, int c0, int n0, float vmax[4])
{
    __syncwarp();

    // ---- phase A: Linear(3->128) -> GroupNorm(8) -> LeakyReLU ----
    #pragma unroll
    for (int q = 0; q < 8; q++) {
        const int n = n0 + q;
        float h[4] = {0.f, 0.f, 0.f, 0.f};
        if (ALL_VALID || n < NN) {
            const float x0 = s.xs[n * 3 + 0];
            const float x1 = s.xs[n * 3 + 1];
            const float x2 = s.xs[n * 3 + 2];
            #pragma unroll
            for (int m = 0; m < 4; m++) {
                const int c = c0 + m;
                h[m] = s.b1[c] + x0 * s.W1[c] + x1 * s.W1[HID + c]
                               + x2 * s.W1[2 * HID + c];
            }
            // GroupNorm: group = 16 channels = 4 consecutive lanes
            float sm = h[0] + h[1] + h[2] + h[3];
            float sq = h[0]*h[0] + h[1]*h[1] + h[2]*h[2] + h[3]*h[3];
            sm += __shfl_xor_sync(0xffffffffu, sm, 1);
            sq += __shfl_xor_sync(0xffffffffu, sq, 1);
            sm += __shfl_xor_sync(0xffffffffu, sm, 2);
            sq += __shfl_xor_sync(0xffffffffu, sq, 2);
            const float mean = sm * (1.f / 16.f);
            const float var  = sq * (1.f / 16.f) - mean * mean;
            const float rstd = rsqrtf(var + 1e-5f);
            #pragma unroll
            for (int m = 0; m < 4; m++) {
                const int c = c0 + m;
                float v = (h[m] - mean) * rstd * s.gg[c] + s.gb[c];
                h[m] = v > 0.f ? v : 0.2f * v;   // LeakyReLU(0.2)
            }
        }
        // swizzled store: rows 4*lane..4*lane+3, col = w*8+q
        const int col  = w * 8 + q;
        const int gp   = ((col >> 2) + lane) & 15;
        const int base = (4 * lane) * 64 + gp * 4 + (col & 3);
        s.HT2[base          ] = h[0];
        s.HT2[base +  64    ] = h[1];
        s.HT2[base + 128    ] = h[2];
        s.HT2[base + 192    ] = h[3];
    }
    __syncwarp();   // warp-local STS -> LDS visibility

    // ---- phase B: h2 = h1 @ W2 + b2 (packed f32x2 over node pairs) ----
    if (ALL_VALID || n0 < NN) {
        // accP[p][m]: nodes (n0+2p, n0+2p+1) x channel c0+m
        ull accP[4][4];
        #pragma unroll
        for (int p = 0; p < 4; p++)
            #pragma unroll
            for (int m = 0; m < 4; m++)
                accP[p][m] = pk2(s.b2[c0 + m], s.b2[c0 + m]);

        for (int jg = 0; jg < 32; jg++) {
            const int g0 = (2 * w     + jg) & 15;   // cols w*8..+3
            const int g1 = (2 * w + 1 + jg) & 15;   // cols w*8+4..+7
            #pragma unroll
            for (int jj = 0; jj < 4; jj++) {
                const int j = jg * 4 + jj;
                const ulonglong2 ha =
                    *reinterpret_cast<const ulonglong2*>(&s.HT2[j * 64 + g0 * 4]);
                const ulonglong2 hb =
                    *reinterpret_cast<const ulonglong2*>(&s.HT2[j * 64 + g1 * 4]);
                const float4 wv =
                    *reinterpret_cast<const float4*>(&s.W2[j * HID + c0]);
                const ull wd0 = pk2(wv.x, wv.x);
                const ull wd1 = pk2(wv.y, wv.y);
                const ull wd2 = pk2(wv.z, wv.z);
                const ull wd3 = pk2(wv.w, wv.w);
                fma2(accP[0][0], ha.x, wd0); fma2(accP[0][1], ha.x, wd1);
                fma2(accP[0][2], ha.x, wd2); fma2(accP[0][3], ha.x, wd3);
                fma2(accP[1][0], ha.y, wd0); fma2(accP[1][1], ha.y, wd1);
                fma2(accP[1][2], ha.y, wd2); fma2(accP[1][3], ha.y, wd3);
                fma2(accP[2][0], hb.x, wd0); fma2(accP[2][1], hb.x, wd1);
                fma2(accP[2][2], hb.x, wd2); fma2(accP[2][3], hb.x, wd3);
                fma2(accP[3][0], hb.y, wd0); fma2(accP[3][1], hb.y, wd1);
                fma2(accP[3][2], hb.y, wd2); fma2(accP[3][3], hb.y, wd3);
            }
        }

        // ---- segment max (valid nodes only) ----
        #pragma unroll
        for (int p = 0; p < 4; p++) {
            const bool v0 = ALL_VALID || (n0 + 2 * p)     < NN;
            const bool v1 = ALL_VALID || (n0 + 2 * p + 1) < NN;
            #pragma unroll
            for (int m = 0; m < 4; m++) {
                float lo, hi;
                upk2(accP[p][m], lo, hi);
                if (v0) vmax[m] = fmaxf(vmax[m], lo);
                if (v1) vmax[m] = fmaxf(vmax[m], hi);
            }
        }
    }
}

__global__ __launch_bounds__(256, 2) void k1_nodes(
    const float* __restrict__ x,  const float* __restrict__ rs,
    const float* __restrict__ W1, const float* __restrict__ b1,
    const float* __restrict__ gn_g, const float* __restrict__ gn_b,
    const float* __restrict__ W2, const float* __restrict__ b2)
{
    extern __shared__ char smem_raw[];
    SmemK1& s = *reinterpret_cast<SmemK1*>(smem_raw);

    const int g    = blockIdx.x;
    const int tid  = threadIdx.x;
    const int lane = tid & 31;
    const int w    = tid >> 5;
    const int c0   = lane * 4;           // this lane's 4 output channels

    // stage weights into shared
    for (int i = tid; i < HID * HID / 4; i += 256)
        reinterpret_cast<float4*>(s.W2)[i] = reinterpret_cast<const float4*>(W2)[i];
    for (int i = tid; i < 3 * HID / 4; i += 256)
        reinterpret_cast<float4*>(s.W1)[i] = reinterpret_cast<const float4*>(W1)[i];
    if (tid < HID) {
        s.b1[tid] = b1[tid];
        s.gg[tid] = gn_g[tid];
        s.gb[tid] = gn_b[tid];
        s.b2[tid] = b2[tid];
    }
    // stage xs = x * roi_scaler for this graph (coalesced; product computed
    // once per element -> bitwise-identical to per-lane recomputation)
    for (int i = tid; i < NN * 3; i += 256)
        s.xs[i] = x[g * (NN * 3) + i] * rs[i];
    __syncthreads();

    float vmax[4] = {-3.4e38f, -3.4e38f, -3.4e38f, -3.4e38f};

    // pass 0: slots 0..63 all valid; pass 1: slots 64..127 need checks
    k1_pass<true >(s, w, lane, c0,      w * 8, vmax);
    k1_pass<false>(s, w, lane, c0, 64 + w * 8, vmax);

    // cross-warp max reduction -> z[g]
    #pragma unroll
    for (int m = 0; m < 4; m++) s.wmax[w][c0 + m] = vmax[m];
    __syncthreads();
    if (tid < HID) {
        float v = s.wmax[0][tid];
        #pragma unroll
        for (int ww = 1; ww < 8; ww++) v = fmaxf(v, s.wmax[ww][tid]);
        g_z[g * HID + tid] = v;
    }
}

// ------------------------------- K2 ----------------------------------------
// p = z @ W3 + b3, 32 rows / block (halves W3 L2 traffic vs 16), thread owns
// cols (tid, tid+256) packed. szd[r][j] holds z duplicated; row-major so
// (j,j+1) is one aligned LDS.128. Epilogue emits per-block column sum/sumsq.
__global__ __launch_bounds__(256) void k2_proj(
    const float* __restrict__ W3, const float* __restrict__ b3)
{
    __shared__ ull szd[K2R][HID];   // 32 KB
    const int blk = blockIdx.x;
    const int r0  = blk * K2R;
    const int tid = threadIdx.x;

    for (int i = tid; i < K2R * HID; i += 256) {
        const int r = i >> 7, j = i & 127;
        const float v = g_z[(r0 + r) * HID + j];
        szd[r][j] = pk2(v, v);
    }
    __syncthreads();

    ull acc2[K2R];
    {
        const float bb0 = b3[tid], bb1 = b3[tid + 256];
        #pragma unroll
        for (int r = 0; r < K2R; r++) acc2[r] = pk2(bb0, bb1);
    }

    for (int j = 0; j < HID; j += 2) {
        const ull wa = pk2(W3[j * P3 + tid],       W3[j * P3 + tid + 256]);
        const ull wb = pk2(W3[(j + 1) * P3 + tid], W3[(j + 1) * P3 + tid + 256]);
        #pragma unroll
        for (int r = 0; r < K2R; r++) {
            // one LDS.128: z[r][j] and z[r][j+1] (each duplicated)
            const ulonglong2 zv =
                *reinterpret_cast<const ulonglong2*>(&szd[r][j]);
            fma2(acc2[r], zv.x, wa);
            fma2(acc2[r], zv.y, wb);
        }
    }

    // write p + accumulate per-block column stats partials
    float ps0 = 0.f, pq0 = 0.f, ps1 = 0.f, pq1 = 0.f;
    #pragma unroll
    for (int r = 0; r < K2R; r++) {
        float lo, hi;
        upk2(acc2[r], lo, hi);
        g_p[(r0 + r) * P3 + tid]       = lo;
        g_p[(r0 + r) * P3 + tid + 256] = hi;
        ps0 += lo; pq0 += lo * lo;
        ps1 += hi; pq1 += hi * hi;
    }
    g_part[blk * P3 + tid]                  = ps0;
    g_part[blk * P3 + tid + 256]            = ps1;
    g_part[K2B * P3 + blk * P3 + tid]       = pq0;
    g_part[K2B * P3 + blk * P3 + tid + 256] = pq1;
}

// ------------------------------- K3 ----------------------------------------
// 4 blocks x 128 threads, one channel per thread; fixed-order partial sum.
__global__ void k3b_stats(const float* __restrict__ bn_g,
                          const float* __restrict__ bn_b)
{
    const int c = blockIdx.x * 128 + threadIdx.x;
    float s = 0.f, sq = 0.f;
    for (int b = 0; b < K2B; b++) {           // fixed order -> deterministic
        s  += g_part[b * P3 + c];
        sq += g_part[K2B * P3 + b * P3 + c];
    }
    const float mean = s * (1.f / 4096.f);
    const float var  = sq * (1.f / 4096.f) - mean * mean;
    const float rstd = rsqrtf(var + 1e-5f);
    const float scale = rstd * bn_g[c];
    g_stats[c]      = scale;
    g_stats[P3 + c] = bn_b[c] - mean * scale;
}

// ------------------------------- K4 ----------------------------------------
// out = L2norm( relu(bn(p)) @ W4 + b4 ), 32 rows / block, 4 cols / thread,
// packed f32x2 over column pairs; activations stored pre-duplicated in smem.
// j unrolled by 2 so each psd read is one LDS.128 (two packed j's) -> smem
// crossbar load halved; FMA pipe is the sole binder.
struct SmemK4 {
    ull   psd[32][P3];   // 128 KB, (p,p) duplicated; [r][j], j pairs 16B-aligned
    float wred[32][8];
    float norms[32];
};

__global__ __launch_bounds__(256, 1) void k4_out(
    const float* __restrict__ W4, const float* __restrict__ b4,
    float* __restrict__ out)
{
    extern __shared__ char smem_raw[];
    SmemK4& s = *reinterpret_cast<SmemK4*>(smem_raw);

    const int r0   = blockIdx.x * 32;
    const int tid  = threadIdx.x;
    const int lane = tid & 31;
    const int w    = tid >> 5;
    const int cb   = tid * 4;

    for (int i = tid; i < 32 * P3; i += 256) {
        const int r = i >> 9, c = i & 511;
        float v = g_p[(r0 + r) * P3 + c];
        v = v * g_stats[c] + g_stats[P3 + c];
        v = v > 0.f ? v : 0.f;
        s.psd[r][c] = pk2(v, v);
    }
    __syncthreads();

    // accP[r][0] = cols (cb, cb+1); accP[r][1] = cols (cb+2, cb+3)
    ull accP[32][2];
    {
        const float4 bv = *reinterpret_cast<const float4*>(b4 + cb);
        #pragma unroll
        for (int r = 0; r < 32; r++) {
            accP[r][0] = pk2(bv.x, bv.y);
            accP[r][1] = pk2(bv.z, bv.w);
        }
    }

    for (int j = 0; j < P3; j += 2) {
        const ulonglong2 wpa =
            *reinterpret_cast<const ulonglong2*>(W4 + j * EMB + cb);
        const ulonglong2 wpb =
            *reinterpret_cast<const ulonglong2*>(W4 + (j + 1) * EMB + cb);
        #pragma unroll
        for (int r = 0; r < 32; r++) {
            // one LDS.128: psd[r][j] and psd[r][j+1]
            const ulonglong2 pv =
                *reinterpret_cast<const ulonglong2*>(&s.psd[r][j]);
            fma2(accP[r][0], wpa.x, pv.x);
            fma2(accP[r][1], wpa.y, pv.x);
            fma2(accP[r][0], wpb.x, pv.y);
            fma2(accP[r][1], wpb.y, pv.y);
        }
    }

    // per-row sum of squares (deterministic tree reductions)
    #pragma unroll
    for (int r = 0; r < 32; r++) {
        float a0, a1, a2, a3;
        upk2(accP[r][0], a0, a1);
        upk2(accP[r][1], a2, a3);
        float sr = a0*a0 + a1*a1 + a2*a2 + a3*a3;
        sr += __shfl_xor_sync(0xffffffffu, sr, 16);
        sr += __shfl_xor_sync(0xffffffffu, sr, 8);
        sr += __shfl_xor_sync(0xffffffffu, sr, 4);
        sr += __shfl_xor_sync(0xffffffffu, sr, 2);
        sr += __shfl_xor_sync(0xffffffffu, sr, 1);
        if (lane == 0) s.wred[r][w] = sr;
    }
    __syncthreads();
    if (tid < 32) {
        float sr = 0.f;
        #pragma unroll
        for (int ww = 0; ww < 8; ww++) sr += s.wred[tid][ww];
        s.norms[tid] = 1.f / fmaxf(sqrtf(sr), 1e-12f);
    }
    __syncthreads();

    #pragma unroll
    for (int r = 0; r < 32; r++) {
        const float inv = s.norms[r];
        float a0, a1, a2, a3;
        upk2(accP[r][0], a0, a1);
        upk2(accP[r][1], a2, a3);
        float4 o;
        o.x = a0 * inv; o.y = a1 * inv; o.z = a2 * inv; o.w = a3 * inv;
        *reinterpret_cast<float4*>(out + (r0 + r) * EMB + cb) = o;
    }
}

// ------------------------------- launch -------------------------------------

extern "C" void kernel_launch(void* const* d_in, const int* in_sizes, int n_in,
                              void* d_out, int out_size)
{
    const float* x   = (const float*)d_in[0];
    const float* rs  = (const float*)d_in[1];
    const float* W1  = (const float*)d_in[2];
    const float* b1  = (const float*)d_in[3];
    const float* gng = (const float*)d_in[4];
    const float* gnb = (const float*)d_in[5];
    const float* W2  = (const float*)d_in[6];
    const float* b2  = (const float*)d_in[7];
    const float* W3  = (const float*)d_in[8];
    const float* b3  = (const float*)d_in[9];
    const float* bng = (const float*)d_in[10];
    const float* bnb = (const float*)d_in[11];
    const float* W4  = (const float*)d_in[12];
    const float* b4  = (const float*)d_in[13];
    float* out = (float*)d_out;

    cudaFuncSetAttribute(k1_nodes, cudaFuncAttributeMaxDynamicSharedMemorySize,
                         (int)sizeof(SmemK1));
    cudaFuncSetAttribute(k4_out, cudaFuncAttributeMaxDynamicSharedMemorySize,
                         (int)sizeof(SmemK4));

    k1_nodes<<<G, 256, sizeof(SmemK1)>>>(x, rs, W1, b1, gng, gnb, W2, b2);
    k2_proj<<<K2B, 256>>>(W3, b3);
    k3b_stats<<<4, 128>>>(bng, bnb);
    k4_out<<<G / 32, 256, sizeof(SmemK4)>>>(W4, b4, out);
}

// round 11
// speedup vs baseline: 1.0266x; 1.0266x over previous
#include <cuda_runtime.h>
#include <math.h>

// ---------------------------------------------------------------------------
// MRIEncoder fused pipeline, fp32 (rev C9: C8 + K4 16-row tile, 2 CTA/SM)
//   K1: per-node  x*roi -> Linear(3,128) -> GroupNorm(8) -> LeakyReLU(0.2)
//       -> Linear(128,128) -> segment max per graph        => g_z [4096,128]
//   K2: p = z @ W3 + b3  (+ per-block column sum/sumsq)    => g_p, g_part
//   K3: batch-norm stat finalize (4 blocks, fixed order)   => g_stats
//   K4: normalize+ReLU -> @W4 + b4 -> row L2 normalize     => out [4096,1024]
// All math is exact fp32 (f32x2 FMA == 2x scalar FFMA bitwise).
// ---------------------------------------------------------------------------

#define G    4096
#define NN   113
#define HID  128
#define P3   512
#define EMB  1024
#define K2R  32                 // rows per k2 block
#define K2B  (G / K2R)          // 128 k2 blocks
#define K4R  16                 // rows per k4 block (2 CTAs/SM)

typedef unsigned long long ull;

__device__ float g_z[G * HID];            // 2 MB
__device__ float g_p[G * P3];             // 8 MB
__device__ float g_part[2 * K2B * P3];    // per-k2-block column sum / sumsq
__device__ float g_stats[2 * P3];         // fused scale / shift

// ---- packed fp32x2 helpers -------------------------------------------------

__device__ __forceinline__ ull pk2(float lo, float hi) {
    ull r;
    asm("mov.b64 %0, {%1, %2};" : "=l"(r) : "f"(lo), "f"(hi));
    return r;
}
__device__ __forceinline__ void upk2(ull v, float& lo, float& hi) {
    asm("mov.b64 {%0, %1}, %2;" : "=f"(lo), "=f"(hi) : "l"(v));
}
// d = a*b + d  (elementwise on two packed fp32 lanes, exact fp32 FMA)
__device__ __forceinline__ void fma2(ull& d, ull a, ull b) {
    asm("fma.rn.f32x2 %0, %1, %2, %0;" : "+l"(d) : "l"(a), "l"(b));
}

// ------------------------------- K1 ----------------------------------------
// Block = one graph, 256 threads (8 warps). Two passes of 64 node slots.
// Warp w owns node slots w*8..w*8+7 of each pass; lane owns output channels
// c0 = lane*4 .. +3.  113 nodes / 8-node granularity = 15 warp-units.
//
// Prologue stages xs[i] = x[g*339+i] * rs[i] into shared; phase A reads xs
// via broadcast LDS. h-tile layout swizzled; phase-B reads warp-uniform.
// Pass 0 (slots 0..63, always valid) compiled with ALL_VALID=true.

struct SmemK1 {
    float W2[HID * HID];     // 64 KB
    float HT2[HID * 64];     // 32 KB
    float W1[3 * HID];
    float b1[HID];
    float gg[HID];
    float gb[HID];
    float b2[HID];
    float xs[NN * 3 + 1];    // x * roi_scaler for this graph
    float wmax[8][HID];
};

template <bool ALL_VALID>
__device__ __forceinline__ void k1_pass(
    SmemK1& s, int w, int lane, int c0, int n0, float vmax[4])
{
    __syncwarp();

    // ---- phase A: Linear(3->128) -> GroupNorm(8) -> LeakyReLU ----
    #pragma unroll
    for (int q = 0; q < 8; q++) {
        const int n = n0 + q;
        float h[4] = {0.f, 0.f, 0.f, 0.f};
        if (ALL_VALID || n < NN) {
            const float x0 = s.xs[n * 3 + 0];
            const float x1 = s.xs[n * 3 + 1];
            const float x2 = s.xs[n * 3 + 2];
            #pragma unroll
            for (int m = 0; m < 4; m++) {
                const int c = c0 + m;
                h[m] = s.b1[c] + x0 * s.W1[c] + x1 * s.W1[HID + c]
                               + x2 * s.W1[2 * HID + c];
            }
            // GroupNorm: group = 16 channels = 4 consecutive lanes
            float sm = h[0] + h[1] + h[2] + h[3];
            float sq = h[0]*h[0] + h[1]*h[1] + h[2]*h[2] + h[3]*h[3];
            sm += __shfl_xor_sync(0xffffffffu, sm, 1);
            sq += __shfl_xor_sync(0xffffffffu, sq, 1);
            sm += __shfl_xor_sync(0xffffffffu, sm, 2);
            sq += __shfl_xor_sync(0xffffffffu, sq, 2);
            const float mean = sm * (1.f / 16.f);
            const float var  = sq * (1.f / 16.f) - mean * mean;
            const float rstd = rsqrtf(var + 1e-5f);
            #pragma unroll
            for (int m = 0; m < 4; m++) {
                const int c = c0 + m;
                float v = (h[m] - mean) * rstd * s.gg[c] + s.gb[c];
                h[m] = v > 0.f ? v : 0.2f * v;   // LeakyReLU(0.2)
            }
        }
        // swizzled store: rows 4*lane..4*lane+3, col = w*8+q
        const int col  = w * 8 + q;
        const int gp   = ((col >> 2) + lane) & 15;
        const int base = (4 * lane) * 64 + gp * 4 + (col & 3);
        s.HT2[base          ] = h[0];
        s.HT2[base +  64    ] = h[1];
        s.HT2[base + 128    ] = h[2];
        s.HT2[base + 192    ] = h[3];
    }
    __syncwarp();   // warp-local STS -> LDS visibility

    // ---- phase B: h2 = h1 @ W2 + b2 (packed f32x2 over node pairs) ----
    if (ALL_VALID || n0 < NN) {
        // accP[p][m]: nodes (n0+2p, n0+2p+1) x channel c0+m
        ull accP[4][4];
        #pragma unroll
        for (int p = 0; p < 4; p++)
            #pragma unroll
            for (int m = 0; m < 4; m++)
                accP[p][m] = pk2(s.b2[c0 + m], s.b2[c0 + m]);

        for (int jg = 0; jg < 32; jg++) {
            const int g0 = (2 * w     + jg) & 15;   // cols w*8..+3
            const int g1 = (2 * w + 1 + jg) & 15;   // cols w*8+4..+7
            #pragma unroll
            for (int jj = 0; jj < 4; jj++) {
                const int j = jg * 4 + jj;
                const ulonglong2 ha =
                    *reinterpret_cast<const ulonglong2*>(&s.HT2[j * 64 + g0 * 4]);
                const ulonglong2 hb =
                    *reinterpret_cast<const ulonglong2*>(&s.HT2[j * 64 + g1 * 4]);
                const float4 wv =
                    *reinterpret_cast<const float4*>(&s.W2[j * HID + c0]);
                const ull wd0 = pk2(wv.x, wv.x);
                const ull wd1 = pk2(wv.y, wv.y);
                const ull wd2 = pk2(wv.z, wv.z);
                const ull wd3 = pk2(wv.w, wv.w);
                fma2(accP[0][0], ha.x, wd0); fma2(accP[0][1], ha.x, wd1);
                fma2(accP[0][2], ha.x, wd2); fma2(accP[0][3], ha.x, wd3);
                fma2(accP[1][0], ha.y, wd0); fma2(accP[1][1], ha.y, wd1);
                fma2(accP[1][2], ha.y, wd2); fma2(accP[1][3], ha.y, wd3);
                fma2(accP[2][0], hb.x, wd0); fma2(accP[2][1], hb.x, wd1);
                fma2(accP[2][2], hb.x, wd2); fma2(accP[2][3], hb.x, wd3);
                fma2(accP[3][0], hb.y, wd0); fma2(accP[3][1], hb.y, wd1);
                fma2(accP[3][2], hb.y, wd2); fma2(accP[3][3], hb.y, wd3);
            }
        }

        // ---- segment max (valid nodes only) ----
        #pragma unroll
        for (int p = 0; p < 4; p++) {
            const bool v0 = ALL_VALID || (n0 + 2 * p)     < NN;
            const bool v1 = ALL_VALID || (n0 + 2 * p + 1) < NN;
            #pragma unroll
            for (int m = 0; m < 4; m++) {
                float lo, hi;
                upk2(accP[p][m], lo, hi);
                if (v0) vmax[m] = fmaxf(vmax[m], lo);
                if (v1) vmax[m] = fmaxf(vmax[m], hi);
            }
        }
    }
}

__global__ __launch_bounds__(256, 2) void k1_nodes(
    const float* __restrict__ x,  const float* __restrict__ rs,
    const float* __restrict__ W1, const float* __restrict__ b1,
    const float* __restrict__ gn_g, const float* __restrict__ gn_b,
    const float* __restrict__ W2, const float* __restrict__ b2)
{
    extern __shared__ char smem_raw[];
    SmemK1& s = *reinterpret_cast<SmemK1*>(smem_raw);

    const int g    = blockIdx.x;
    const int tid  = threadIdx.x;
    const int lane = tid & 31;
    const int w    = tid >> 5;
    const int c0   = lane * 4;           // this lane's 4 output channels

    // stage weights into shared
    for (int i = tid; i < HID * HID / 4; i += 256)
        reinterpret_cast<float4*>(s.W2)[i] = reinterpret_cast<const float4*>(W2)[i];
    for (int i = tid; i < 3 * HID / 4; i += 256)
        reinterpret_cast<float4*>(s.W1)[i] = reinterpret_cast<const float4*>(W1)[i];
    if (tid < HID) {
        s.b1[tid] = b1[tid];
        s.gg[tid] = gn_g[tid];
        s.gb[tid] = gn_b[tid];
        s.b2[tid] = b2[tid];
    }
    // stage xs = x * roi_scaler for this graph (coalesced; computed once)
    for (int i = tid; i < NN * 3; i += 256)
        s.xs[i] = x[g * (NN * 3) + i] * rs[i];
    __syncthreads();

    float vmax[4] = {-3.4e38f, -3.4e38f, -3.4e38f, -3.4e38f};

    // pass 0: slots 0..63 all valid; pass 1: slots 64..127 need checks
    k1_pass<true >(s, w, lane, c0,      w * 8, vmax);
    k1_pass<false>(s, w, lane, c0, 64 + w * 8, vmax);

    // cross-warp max reduction -> z[g]
    #pragma unroll
    for (int m = 0; m < 4; m++) s.wmax[w][c0 + m] = vmax[m];
    __syncthreads();
    if (tid < HID) {
        float v = s.wmax[0][tid];
        #pragma unroll
        for (int ww = 1; ww < 8; ww++) v = fmaxf(v, s.wmax[ww][tid]);
        g_z[g * HID + tid] = v;
    }
}

// ------------------------------- K2 ----------------------------------------
// p = z @ W3 + b3, 32 rows / block, thread owns cols (tid, tid+256) packed.
// szd[r][j] duplicated, row-major so (j,j+1) is one aligned LDS.128.
// Epilogue emits per-block column sum/sumsq.
__global__ __launch_bounds__(256) void k2_proj(
    const float* __restrict__ W3, const float* __restrict__ b3)
{
    __shared__ ull szd[K2R][HID];   // 32 KB
    const int blk = blockIdx.x;
    const int r0  = blk * K2R;
    const int tid = threadIdx.x;

    for (int i = tid; i < K2R * HID; i += 256) {
        const int r = i >> 7, j = i & 127;
        const float v = g_z[(r0 + r) * HID + j];
        szd[r][j] = pk2(v, v);
    }
    __syncthreads();

    ull acc2[K2R];
    {
        const float bb0 = b3[tid], bb1 = b3[tid + 256];
        #pragma unroll
        for (int r = 0; r < K2R; r++) acc2[r] = pk2(bb0, bb1);
    }

    for (int j = 0; j < HID; j += 2) {
        const ull wa = pk2(W3[j * P3 + tid],       W3[j * P3 + tid + 256]);
        const ull wb = pk2(W3[(j + 1) * P3 + tid], W3[(j + 1) * P3 + tid + 256]);
        #pragma unroll
        for (int r = 0; r < K2R; r++) {
            const ulonglong2 zv =
                *reinterpret_cast<const ulonglong2*>(&szd[r][j]);
            fma2(acc2[r], zv.x, wa);
            fma2(acc2[r], zv.y, wb);
        }
    }

    // write p + accumulate per-block column stats partials
    float ps0 = 0.f, pq0 = 0.f, ps1 = 0.f, pq1 = 0.f;
    #pragma unroll
    for (int r = 0; r < K2R; r++) {
        float lo, hi;
        upk2(acc2[r], lo, hi);
        g_p[(r0 + r) * P3 + tid]       = lo;
        g_p[(r0 + r) * P3 + tid + 256] = hi;
        ps0 += lo; pq0 += lo * lo;
        ps1 += hi; pq1 += hi * hi;
    }
    g_part[blk * P3 + tid]                  = ps0;
    g_part[blk * P3 + tid + 256]            = ps1;
    g_part[K2B * P3 + blk * P3 + tid]       = pq0;
    g_part[K2B * P3 + blk * P3 + tid + 256] = pq1;
}

// ------------------------------- K3 ----------------------------------------
// 4 blocks x 128 threads, one channel per thread; fixed-order partial sum.
__global__ void k3b_stats(const float* __restrict__ bn_g,
                          const float* __restrict__ bn_b)
{
    const int c = blockIdx.x * 128 + threadIdx.x;
    float s = 0.f, sq = 0.f;
    for (int b = 0; b < K2B; b++) {           // fixed order -> deterministic
        s  += g_part[b * P3 + c];
        sq += g_part[K2B * P3 + b * P3 + c];
    }
    const float mean = s * (1.f / 4096.f);
    const float var  = sq * (1.f / 4096.f) - mean * mean;
    const float rstd = rsqrtf(var + 1e-5f);
    const float scale = rstd * bn_g[c];
    g_stats[c]      = scale;
    g_stats[P3 + c] = bn_b[c] - mean * scale;
}

// ------------------------------- K4 ----------------------------------------
// out = L2norm( relu(bn(p)) @ W4 + b4 ), 16 rows / block, 4 cols / thread.
// rev C9: tile halved (was 32 rows) so accumulators fit in 64 regs and smem
// in 64 KB -> __launch_bounds__(256,2) gives 2 CTAs/SM (occ 25%), hiding the
// LDS(29cy)/LDG-L2(234cy) latency that capped the 1-CTA version at issue=36%.
// W4 L2 traffic doubles to 512 MB (~45us at LTS cap) but stays under the
// 63us FMA floor, so FMA binds once latency is hidden.
struct SmemK4 {
    ull   psd[K4R][P3];   // 64 KB, (p,p) duplicated; [r][j], pairs 16B-aligned
    float wred[K4R][8];
    float norms[K4R];
};

__global__ __launch_bounds__(256, 2) void k4_out(
    const float* __restrict__ W4, const float* __restrict__ b4,
    float* __restrict__ out)
{
    extern __shared__ char smem_raw[];
    SmemK4& s = *reinterpret_cast<SmemK4*>(smem_raw);

    const int r0   = blockIdx.x * K4R;
    const int tid  = threadIdx.x;
    const int lane = tid & 31;
    const int w    = tid >> 5;
    const int cb   = tid * 4;

    for (int i = tid; i < K4R * P3; i += 256) {
        const int r = i >> 9, c = i & 511;
        float v = g_p[(r0 + r) * P3 + c];
        v = v * g_stats[c] + g_stats[P3 + c];
        v = v > 0.f ? v : 0.f;
        s.psd[r][c] = pk2(v, v);
    }
    __syncthreads();

    // accP[r][0] = cols (cb, cb+1); accP[r][1] = cols (cb+2, cb+3)
    ull accP[K4R][2];
    {
        const float4 bv = *reinterpret_cast<const float4*>(b4 + cb);
        #pragma unroll
        for (int r = 0; r < K4R; r++) {
            accP[r][0] = pk2(bv.x, bv.y);
            accP[r][1] = pk2(bv.z, bv.w);
        }
    }

    for (int j = 0; j < P3; j += 2) {
        const ulonglong2 wpa =
            *reinterpret_cast<const ulonglong2*>(W4 + j * EMB + cb);
        const ulonglong2 wpb =
            *reinterpret_cast<const ulonglong2*>(W4 + (j + 1) * EMB + cb);
        #pragma unroll
        for (int r = 0; r < K4R; r++) {
            // one LDS.128: psd[r][j] and psd[r][j+1]
            const ulonglong2 pv =
                *reinterpret_cast<const ulonglong2*>(&s.psd[r][j]);
            fma2(accP[r][0], wpa.x, pv.x);
            fma2(accP[r][1], wpa.y, pv.x);
            fma2(accP[r][0], wpb.x, pv.y);
            fma2(accP[r][1], wpb.y, pv.y);
        }
    }

    // per-row sum of squares (deterministic tree reductions)
    #pragma unroll
    for (int r = 0; r < K4R; r++) {
        float a0, a1, a2, a3;
        upk2(accP[r][0], a0, a1);
        upk2(accP[r][1], a2, a3);
        float sr = a0*a0 + a1*a1 + a2*a2 + a3*a3;
        sr += __shfl_xor_sync(0xffffffffu, sr, 16);
        sr += __shfl_xor_sync(0xffffffffu, sr, 8);
        sr += __shfl_xor_sync(0xffffffffu, sr, 4);
        sr += __shfl_xor_sync(0xffffffffu, sr, 2);
        sr += __shfl_xor_sync(0xffffffffu, sr, 1);
        if (lane == 0) s.wred[r][w] = sr;
    }
    __syncthreads();
    if (tid < K4R) {
        float sr = 0.f;
        #pragma unroll
        for (int ww = 0; ww < 8; ww++) sr += s.wred[tid][ww];
        s.norms[tid] = 1.f / fmaxf(sqrtf(sr), 1e-12f);
    }
    __syncthreads();

    #pragma unroll
    for (int r = 0; r < K4R; r++) {
        const float inv = s.norms[r];
        float a0, a1, a2, a3;
        upk2(accP[r][0], a0, a1);
        upk2(accP[r][1], a2, a3);
        float4 o;
        o.x = a0 * inv; o.y = a1 * inv; o.z = a2 * inv; o.w = a3 * inv;
        *reinterpret_cast<float4*>(out + (r0 + r) * EMB + cb) = o;
    }
}

// ------------------------------- launch -------------------------------------

extern "C" void kernel_launch(void* const* d_in, const int* in_sizes, int n_in,
                              void* d_out, int out_size)
{
    const float* x   = (const float*)d_in[0];
    const float* rs  = (const float*)d_in[1];
    const float* W1  = (const float*)d_in[2];
    const float* b1  = (const float*)d_in[3];
    const float* gng = (const float*)d_in[4];
    const float* gnb = (const float*)d_in[5];
    const float* W2  = (const float*)d_in[6];
    const float* b2  = (const float*)d_in[7];
    const float* W3  = (const float*)d_in[8];
    const float* b3  = (const float*)d_in[9];
    const float* bng = (const float*)d_in[10];
    const float* bnb = (const float*)d_in[11];
    const float* W4  = (const float*)d_in[12];
    const float* b4  = (const float*)d_in[13];
    float* out = (float*)d_out;

    cudaFuncSetAttribute(k1_nodes, cudaFuncAttributeMaxDynamicSharedMemorySize,
                         (int)sizeof(SmemK1));
    cudaFuncSetAttribute(k4_out, cudaFuncAttributeMaxDynamicSharedMemorySize,
                         (int)sizeof(SmemK4));

    k1_nodes<<<G, 256, sizeof(SmemK1)>>>(x, rs, W1, b1, gng, gnb, W2, b2);
    k2_proj<<<K2B, 256>>>(W3, b3);
    k3b_stats<<<4, 128>>>(bng, bnb);
    k4_out<<<G / K4R, 256, sizeof(SmemK4)>>>(W4, b4, out);
}

// round 15
// speedup vs baseline: 1.0361x; 1.0093x over previous
#include <cuda_runtime.h>
#include <math.h>

// ---------------------------------------------------------------------------
// MRIEncoder fused pipeline, fp32 (rev C10: C9 + transposed p, K4 row-pair
// packing with raw (non-duplicated) activation tile -> LDS count halved)
//   K1: per-node  x*roi -> Linear(3,128) -> GroupNorm(8) -> LeakyReLU(0.2)
//       -> Linear(128,128) -> segment max per graph        => g_z [4096,128]
//   K2: p = z @ W3 + b3 (stored TRANSPOSED [col][row])     => g_pt, g_part
//   K3: batch-norm stat finalize (4 blocks, fixed order)   => g_stats
//   K4: normalize+ReLU -> @W4 + b4 -> row L2 normalize     => out [4096,1024]
// All math is exact fp32 (f32x2 FMA == 2x scalar FFMA bitwise).
// ---------------------------------------------------------------------------

#define G    4096
#define NN   113
#define HID  128
#define P3   512
#define EMB  1024
#define K2R  32                 // rows per k2 block
#define K2B  (G / K2R)          // 128 k2 blocks
#define K4R  16                 // rows per k4 block

typedef unsigned long long ull;

__device__ float g_z[G * HID];            // 2 MB
__device__ float g_pt[P3 * G];            // 8 MB, TRANSPOSED: [col][row]
__device__ float g_part[2 * K2B * P3];    // per-k2-block column sum / sumsq
__device__ float g_stats[2 * P3];         // fused scale / shift

// ---- packed fp32x2 helpers -------------------------------------------------

__device__ __forceinline__ ull pk2(float lo, float hi) {
    ull r;
    asm("mov.b64 %0, {%1, %2};" : "=l"(r) : "f"(lo), "f"(hi));
    return r;
}
__device__ __forceinline__ void upk2(ull v, float& lo, float& hi) {
    asm("mov.b64 {%0, %1}, %2;" : "=f"(lo), "=f"(hi) : "l"(v));
}
// d = a*b + d  (elementwise on two packed fp32 lanes, exact fp32 FMA)
__device__ __forceinline__ void fma2(ull& d, ull a, ull b) {
    asm("fma.rn.f32x2 %0, %1, %2, %0;" : "+l"(d) : "l"(a), "l"(b));
}

// ------------------------------- K1 (unchanged) -----------------------------

struct SmemK1 {
    float W2[HID * HID];     // 64 KB
    float HT2[HID * 64];     // 32 KB
    float W1[3 * HID];
    float b1[HID];
    float gg[HID];
    float gb[HID];
    float b2[HID];
    float xs[NN * 3 + 1];    // x * roi_scaler for this graph
    float wmax[8][HID];
};

template <bool ALL_VALID>
__device__ __forceinline__ void k1_pass(
    SmemK1& s, int w, int lane, int c0, int n0, float vmax[4])
{
    __syncwarp();

    // ---- phase A: Linear(3->128) -> GroupNorm(8) -> LeakyReLU ----
    #pragma unroll
    for (int q = 0; q < 8; q++) {
        const int n = n0 + q;
        float h[4] = {0.f, 0.f, 0.f, 0.f};
        if (ALL_VALID || n < NN) {
            const float x0 = s.xs[n * 3 + 0];
            const float x1 = s.xs[n * 3 + 1];
            const float x2 = s.xs[n * 3 + 2];
            #pragma unroll
            for (int m = 0; m < 4; m++) {
                const int c = c0 + m;
                h[m] = s.b1[c] + x0 * s.W1[c] + x1 * s.W1[HID + c]
                               + x2 * s.W1[2 * HID + c];
            }
            float sm = h[0] + h[1] + h[2] + h[3];
            float sq = h[0]*h[0] + h[1]*h[1] + h[2]*h[2] + h[3]*h[3];
            sm += __shfl_xor_sync(0xffffffffu, sm, 1);
            sq += __shfl_xor_sync(0xffffffffu, sq, 1);
            sm += __shfl_xor_sync(0xffffffffu, sm, 2);
            sq += __shfl_xor_sync(0xffffffffu, sq, 2);
            const float mean = sm * (1.f / 16.f);
            const float var  = sq * (1.f / 16.f) - mean * mean;
            const float rstd = rsqrtf(var + 1e-5f);
            #pragma unroll
            for (int m = 0; m < 4; m++) {
                const int c = c0 + m;
                float v = (h[m] - mean) * rstd * s.gg[c] + s.gb[c];
                h[m] = v > 0.f ? v : 0.2f * v;   // LeakyReLU(0.2)
            }
        }
        const int col  = w * 8 + q;
        const int gp   = ((col >> 2) + lane) & 15;
        const int base = (4 * lane) * 64 + gp * 4 + (col & 3);
        s.HT2[base          ] = h[0];
        s.HT2[base +  64    ] = h[1];
        s.HT2[base + 128    ] = h[2];
        s.HT2[base + 192    ] = h[3];
    }
    __syncwarp();

    // ---- phase B: h2 = h1 @ W2 + b2 (packed f32x2 over node pairs) ----
    if (ALL_VALID || n0 < NN) {
        ull accP[4][4];
        #pragma unroll
        for (int p = 0; p < 4; p++)
            #pragma unroll
            for (int m = 0; m < 4; m++)
                accP[p][m] = pk2(s.b2[c0 + m], s.b2[c0 + m]);

        for (int jg = 0; jg < 32; jg++) {
            const int g0 = (2 * w     + jg) & 15;
            const int g1 = (2 * w + 1 + jg) & 15;
            #pragma unroll
            for (int jj = 0; jj < 4; jj++) {
                const int j = jg * 4 + jj;
                const ulonglong2 ha =
                    *reinterpret_cast<const ulonglong2*>(&s.HT2[j * 64 + g0 * 4]);
                const ulonglong2 hb =
                    *reinterpret_cast<const ulonglong2*>(&s.HT2[j * 64 + g1 * 4]);
                const float4 wv =
                    *reinterpret_cast<const float4*>(&s.W2[j * HID + c0]);
                const ull wd0 = pk2(wv.x, wv.x);
                const ull wd1 = pk2(wv.y, wv.y);
                const ull wd2 = pk2(wv.z, wv.z);
                const ull wd3 = pk2(wv.w, wv.w);
                fma2(accP[0][0], ha.x, wd0); fma2(accP[0][1], ha.x, wd1);
                fma2(accP[0][2], ha.x, wd2); fma2(accP[0][3], ha.x, wd3);
                fma2(accP[1][0], ha.y, wd0); fma2(accP[1][1], ha.y, wd1);
                fma2(accP[1][2], ha.y, wd2); fma2(accP[1][3], ha.y, wd3);
                fma2(accP[2][0], hb.x, wd0); fma2(accP[2][1], hb.x, wd1);
                fma2(accP[2][2], hb.x, wd2); fma2(accP[2][3], hb.x, wd3);
                fma2(accP[3][0], hb.y, wd0); fma2(accP[3][1], hb.y, wd1);
                fma2(accP[3][2], hb.y, wd2); fma2(accP[3][3], hb.y, wd3);
            }
        }

        #pragma unroll
        for (int p = 0; p < 4; p++) {
            const bool v0 = ALL_VALID || (n0 + 2 * p)     < NN;
            const bool v1 = ALL_VALID || (n0 + 2 * p + 1) < NN;
            #pragma unroll
            for (int m = 0; m < 4; m++) {
                float lo, hi;
                upk2(accP[p][m], lo, hi);
                if (v0) vmax[m] = fmaxf(vmax[m], lo);
                if (v1) vmax[m] = fmaxf(vmax[m], hi);
            }
        }
    }
}

__global__ __launch_bounds__(256, 2) void k1_nodes(
    const float* __restrict__ x,  const float* __restrict__ rs,
    const float* __restrict__ W1, const float* __restrict__ b1,
    const float* __restrict__ gn_g, const float* __restrict__ gn_b,
    const float* __restrict__ W2, const float* __restrict__ b2)
{
    extern __shared__ char smem_raw[];
    SmemK1& s = *reinterpret_cast<SmemK1*>(smem_raw);

    const int g    = blockIdx.x;
    const int tid  = threadIdx.x;
    const int lane = tid & 31;
    const int w    = tid >> 5;
    const int c0   = lane * 4;

    for (int i = tid; i < HID * HID / 4; i += 256)
        reinterpret_cast<float4*>(s.W2)[i] = reinterpret_cast<const float4*>(W2)[i];
    for (int i = tid; i < 3 * HID / 4; i += 256)
        reinterpret_cast<float4*>(s.W1)[i] = reinterpret_cast<const float4*>(W1)[i];
    if (tid < HID) {
        s.b1[tid] = b1[tid];
        s.gg[tid] = gn_g[tid];
        s.gb[tid] = gn_b[tid];
        s.b2[tid] = b2[tid];
    }
    for (int i = tid; i < NN * 3; i += 256)
        s.xs[i] = x[g * (NN * 3) + i] * rs[i];
    __syncthreads();

    float vmax[4] = {-3.4e38f, -3.4e38f, -3.4e38f, -3.4e38f};

    k1_pass<true >(s, w, lane, c0,      w * 8, vmax);
    k1_pass<false>(s, w, lane, c0, 64 + w * 8, vmax);

    #pragma unroll
    for (int m = 0; m < 4; m++) s.wmax[w][c0 + m] = vmax[m];
    __syncthreads();
    if (tid < HID) {
        float v = s.wmax[0][tid];
        #pragma unroll
        for (int ww = 1; ww < 8; ww++) v = fmaxf(v, s.wmax[ww][tid]);
        g_z[g * HID + tid] = v;
    }
}

// ------------------------------- K2 ----------------------------------------
// p = z @ W3 + b3, 32 rows / block, thread owns cols (tid, tid+256) packed.
// Output stored TRANSPOSED: g_pt[col][row], written as float4 row-quads per
// lane (16B per lane into distinct lines; ~2x sector inflation on 8MB, ~1us).
// Epilogue also emits per-block column sum/sumsq (same ascending-row order).
__global__ __launch_bounds__(256) void k2_proj(
    const float* __restrict__ W3, const float* __restrict__ b3)
{
    __shared__ ull szd[K2R][HID];   // 32 KB
    const int blk = blockIdx.x;
    const int r0  = blk * K2R;
    const int tid = threadIdx.x;

    for (int i = tid; i < K2R * HID; i += 256) {
        const int r = i >> 7, j = i & 127;
        const float v = g_z[(r0 + r) * HID + j];
        szd[r][j] = pk2(v, v);
    }
    __syncthreads();

    ull acc2[K2R];
    {
        const float bb0 = b3[tid], bb1 = b3[tid + 256];
        #pragma unroll
        for (int r = 0; r < K2R; r++) acc2[r] = pk2(bb0, bb1);
    }

    for (int j = 0; j < HID; j += 2) {
        const ull wa = pk2(W3[j * P3 + tid],       W3[j * P3 + tid + 256]);
        const ull wb = pk2(W3[(j + 1) * P3 + tid], W3[(j + 1) * P3 + tid + 256]);
        #pragma unroll
        for (int r = 0; r < K2R; r++) {
            const ulonglong2 zv =
                *reinterpret_cast<const ulonglong2*>(&szd[r][j]);
            fma2(acc2[r], zv.x, wa);
            fma2(acc2[r], zv.y, wb);
        }
    }

    // transposed write + per-block column stats (ascending r order kept)
    float ps0 = 0.f, pq0 = 0.f, ps1 = 0.f, pq1 = 0.f;
    #pragma unroll
    for (int rb = 0; rb < K2R; rb += 4) {
        float lo[4], hi[4];
        #pragma unroll
        for (int k = 0; k < 4; k++) {
            upk2(acc2[rb + k], lo[k], hi[k]);
            ps0 += lo[k]; pq0 += lo[k] * lo[k];
            ps1 += hi[k]; pq1 += hi[k] * hi[k];
        }
        float4 v0; v0.x = lo[0]; v0.y = lo[1]; v0.z = lo[2]; v0.w = lo[3];
        float4 v1; v1.x = hi[0]; v1.y = hi[1]; v1.z = hi[2]; v1.w = hi[3];
        *reinterpret_cast<float4*>(&g_pt[(size_t)tid * G + r0 + rb])         = v0;
        *reinterpret_cast<float4*>(&g_pt[(size_t)(tid + 256) * G + r0 + rb]) = v1;
    }
    g_part[blk * P3 + tid]                  = ps0;
    g_part[blk * P3 + tid + 256]            = ps1;
    g_part[K2B * P3 + blk * P3 + tid]       = pq0;
    g_part[K2B * P3 + blk * P3 + tid + 256] = pq1;
}

// ------------------------------- K3 (unchanged) -----------------------------
__global__ void k3b_stats(const float* __restrict__ bn_g,
                          const float* __restrict__ bn_b)
{
    const int c = blockIdx.x * 128 + threadIdx.x;
    float s = 0.f, sq = 0.f;
    for (int b = 0; b < K2B; b++) {           // fixed order -> deterministic
        s  += g_part[b * P3 + c];
        sq += g_part[K2B * P3 + b * P3 + c];
    }
    const float mean = s * (1.f / 4096.f);
    const float var  = sq * (1.f / 4096.f) - mean * mean;
    const float rstd = rsqrtf(var + 1e-5f);
    const float scale = rstd * bn_g[c];
    g_stats[c]      = scale;
    g_stats[P3 + c] = bn_b[c] - mean * scale;
}

// ------------------------------- K4 ----------------------------------------
// out = L2norm( relu(bn(p)) @ W4 + b4 ), 16 rows / block, 4 cols / thread,
// f32x2 packed over ROW pairs: psdT[j][16] holds raw activations transposed;
// per j, 4 broadcast LDS.128 deliver all 8 packed row-pairs directly (no
// duplication on the broadcast operand). W4's 4 per-thread columns are
// duplicated via 4 mov.b64 on the alu pipe. Per j: 4 LDS + 1 LDG + 4 mov +
// 32 fma2 (was 8 LDS + 1 LDG + 32 fma2) -> L1/MIO pressure halved.
struct SmemK4 {
    float psdT[P3][K4R];  // 32 KB, [j][r]; row-quads 16B-aligned
    float wred[K4R][8];
    float norms[K4R];
};

__global__ __launch_bounds__(256, 2) void k4_out(
    const float* __restrict__ W4, const float* __restrict__ b4,
    float* __restrict__ out)
{
    extern __shared__ char smem_raw[];
    SmemK4& s = *reinterpret_cast<SmemK4*>(smem_raw);

    const int r0   = blockIdx.x * K4R;
    const int tid  = threadIdx.x;
    const int lane = tid & 31;
    const int w    = tid >> 5;
    const int cb   = tid * 4;

    // prologue: read transposed p (64B-contiguous per col), BN+relu, STS
    // (banks 16c+r span all 32 -> conflict-free)
    for (int i = tid; i < P3 * K4R; i += 256) {
        const int c = i >> 4, r = i & 15;
        float v = g_pt[(size_t)c * G + r0 + r];
        v = v * g_stats[c] + g_stats[P3 + c];
        s.psdT[c][r] = v > 0.f ? v : 0.f;
    }
    __syncthreads();

    // accR[rp][c]: rows (2rp, 2rp+1) packed x column cb+c
    ull accR[8][4];
    {
        const float4 bv = *reinterpret_cast<const float4*>(b4 + cb);
        #pragma unroll
        for (int rp = 0; rp < 8; rp++) {
            accR[rp][0] = pk2(bv.x, bv.x);
            accR[rp][1] = pk2(bv.y, bv.y);
            accR[rp][2] = pk2(bv.z, bv.z);
            accR[rp][3] = pk2(bv.w, bv.w);
        }
    }

    #pragma unroll 2
    for (int j = 0; j < P3; j++) {
        const float4 wv = *reinterpret_cast<const float4*>(W4 + j * EMB + cb);
        const ull wd0 = pk2(wv.x, wv.x);
        const ull wd1 = pk2(wv.y, wv.y);
        const ull wd2 = pk2(wv.z, wv.z);
        const ull wd3 = pk2(wv.w, wv.w);
        // 4 broadcast LDS.128: rows 0..15 as 8 packed pairs
        const ulonglong2 p01 =
            *reinterpret_cast<const ulonglong2*>(&s.psdT[j][0]);
        const ulonglong2 p23 =
            *reinterpret_cast<const ulonglong2*>(&s.psdT[j][4]);
        const ulonglong2 p45 =
            *reinterpret_cast<const ulonglong2*>(&s.psdT[j][8]);
        const ulonglong2 p67 =
            *reinterpret_cast<const ulonglong2*>(&s.psdT[j][12]);
        fma2(accR[0][0], p01.x, wd0); fma2(accR[0][1], p01.x, wd1);
        fma2(accR[0][2], p01.x, wd2); fma2(accR[0][3], p01.x, wd3);
        fma2(accR[1][0], p01.y, wd0); fma2(accR[1][1], p01.y, wd1);
        fma2(accR[1][2], p01.y, wd2); fma2(accR[1][3], p01.y, wd3);
        fma2(accR[2][0], p23.x, wd0); fma2(accR[2][1], p23.x, wd1);
        fma2(accR[2][2], p23.x, wd2); fma2(accR[2][3], p23.x, wd3);
        fma2(accR[3][0], p23.y, wd0); fma2(accR[3][1], p23.y, wd1);
        fma2(accR[3][2], p23.y, wd2); fma2(accR[3][3], p23.y, wd3);
        fma2(accR[4][0], p45.x, wd0); fma2(accR[4][1], p45.x, wd1);
        fma2(accR[4][2], p45.x, wd2); fma2(accR[4][3], p45.x, wd3);
        fma2(accR[5][0], p45.y, wd0); fma2(accR[5][1], p45.y, wd1);
        fma2(accR[5][2], p45.y, wd2); fma2(accR[5][3], p45.y, wd3);
        fma2(accR[6][0], p67.x, wd0); fma2(accR[6][1], p67.x, wd1);
        fma2(accR[6][2], p67.x, wd2); fma2(accR[6][3], p67.x, wd3);
        fma2(accR[7][0], p67.y, wd0); fma2(accR[7][1], p67.y, wd1);
        fma2(accR[7][2], p67.y, wd2); fma2(accR[7][3], p67.y, wd3);
    }

    // per-row sum of squares (rows 2rp / 2rp+1 in lo/hi lanes)
    #pragma unroll
    for (int rp = 0; rp < 8; rp++) {
        float l[4], h[4];
        #pragma unroll
        for (int c = 0; c < 4; c++) upk2(accR[rp][c], l[c], h[c]);
        float s0 = l[0]*l[0] + l[1]*l[1] + l[2]*l[2] + l[3]*l[3];
        float s1 = h[0]*h[0] + h[1]*h[1] + h[2]*h[2] + h[3]*h[3];
        s0 += __shfl_xor_sync(0xffffffffu, s0, 16);
        s1 += __shfl_xor_sync(0xffffffffu, s1, 16);
        s0 += __shfl_xor_sync(0xffffffffu, s0, 8);
        s1 += __shfl_xor_sync(0xffffffffu, s1, 8);
        s0 += __shfl_xor_sync(0xffffffffu, s0, 4);
        s1 += __shfl_xor_sync(0xffffffffu, s1, 4);
        s0 += __shfl_xor_sync(0xffffffffu, s0, 2);
        s1 += __shfl_xor_sync(0xffffffffu, s1, 2);
        s0 += __shfl_xor_sync(0xffffffffu, s0, 1);
        s1 += __shfl_xor_sync(0xffffffffu, s1, 1);
        if (lane == 0) {
            s.wred[2 * rp][w]     = s0;
            s.wred[2 * rp + 1][w] = s1;
        }
    }
    __syncthreads();
    if (tid < K4R) {
        float sr = 0.f;
        #pragma unroll
        for (int ww = 0; ww < 8; ww++) sr += s.wred[tid][ww];
        s.norms[tid] = 1.f / fmaxf(sqrtf(sr), 1e-12f);
    }
    __syncthreads();

    #pragma unroll
    for (int rp = 0; rp < 8; rp++) {
        const float inv0 = s.norms[2 * rp];
        const float inv1 = s.norms[2 * rp + 1];
        float l[4], h[4];
        #pragma unroll
        for (int c = 0; c < 4; c++) upk2(accR[rp][c], l[c], h[c]);
        float4 o0, o1;
        o0.x = l[0] * inv0; o0.y = l[1] * inv0; o0.z = l[2] * inv0; o0.w = l[3] * inv0;
        o1.x = h[0] * inv1; o1.y = h[1] * inv1; o1.z = h[2] * inv1; o1.w = h[3] * inv1;
        *reinterpret_cast<float4*>(out + (size_t)(r0 + 2 * rp) * EMB + cb)     = o0;
        *reinterpret_cast<float4*>(out + (size_t)(r0 + 2 * rp + 1) * EMB + cb) = o1;
    }
}

// ------------------------------- launch -------------------------------------

extern "C" void kernel_launch(void* const* d_in, const int* in_sizes, int n_in,
                              void* d_out, int out_size)
{
    const float* x   = (const float*)d_in[0];
    const float* rs  = (const float*)d_in[1];
    const float* W1  = (const float*)d_in[2];
    const float* b1  = (const float*)d_in[3];
    const float* gng = (const float*)d_in[4];
    const float* gnb = (const float*)d_in[5];
    const float* W2  = (const float*)d_in[6];
    const float* b2  = (const float*)d_in[7];
    const float* W3  = (const float*)d_in[8];
    const float* b3  = (const float*)d_in[9];
    const float* bng = (const float*)d_in[10];
    const float* bnb = (const float*)d_in[11];
    const float* W4  = (const float*)d_in[12];
    const float* b4  = (const float*)d_in[13];
    float* out = (float*)d_out;

    cudaFuncSetAttribute(k1_nodes, cudaFuncAttributeMaxDynamicSharedMemorySize,
                         (int)sizeof(SmemK1));
    cudaFuncSetAttribute(k4_out, cudaFuncAttributeMaxDynamicSharedMemorySize,
                         (int)sizeof(SmemK4));

    k1_nodes<<<G, 256, sizeof(SmemK1)>>>(x, rs, W1, b1, gng, gnb, W2, b2);
    k2_proj<<<K2B, 256>>>(W3, b3);
    k3b_stats<<<4, 128>>>(bng, bnb);
    k4_out<<<G / K4R, 256, sizeof(SmemK4)>>>(W4, b4, out);
}